// round 3
// baseline (speedup 1.0000x reference)
#include <cuda_runtime.h>
#include <cstdint>

// ---------------- problem dims ----------------
#define T_DIM 256
#define HW    128
#define HW2   (HW*HW)
#define KW    129      // half-spectrum bins along W (Hermitian)
#define KWS   132      // padded row stride (float2)
#define BD    2

// ---------------- device scratch ----------------
__device__ static float  d_tmp [(size_t)BD*T_DIM*HW*HW];
__device__ static float2 d_bufA[(size_t)BD*T_DIM*HW*KWS];
__device__ static float2 d_bufB[(size_t)BD*T_DIM*T_DIM*KWS];
__device__ static float2 d_W512[256];                       // exp(-2*pi*i*k/512)
__device__ static float2 d_W256[256];                       // exp(-2*pi*i*k/256)
__device__ static int    d_cols[2][256][256];
__device__ static float  d_vals[2][256][256];
__device__ static int    d_cnt [2][256];

// ---------------- complex helpers ----------------
static __device__ __forceinline__ float2 cadd(float2 a, float2 b){ return make_float2(a.x+b.x, a.y+b.y); }
static __device__ __forceinline__ float2 csub(float2 a, float2 b){ return make_float2(a.x-b.x, a.y-b.y); }
static __device__ __forceinline__ float2 cmul(float2 a, float2 b){ return make_float2(a.x*b.x - a.y*b.y, a.x*b.y + a.y*b.x); }
static __device__ __forceinline__ float2 cmulc(float2 a, float2 b){ return make_float2(a.x*b.x + a.y*b.y, a.y*b.x - a.x*b.y); } // a*conj(b)
static __device__ __forceinline__ float2 rot_mi(float2 a){ return make_float2(a.y, -a.x); }
static __device__ __forceinline__ float2 rot_pi(float2 a){ return make_float2(-a.y, a.x); }

static __device__ __forceinline__ int brev8(int i){ return __brev((unsigned)i) >> 24; }
static __device__ __forceinline__ int brev9(int i){ return __brev((unsigned)i) >> 23; }

// bit-reverse(4-bit) table
__device__ static const int BR4[16] = {0,8,4,12,2,10,6,14,1,9,5,13,3,11,7,15};

// W16^n = exp(-2*pi*i*n/16), n=0..7 (hardcoded)
static __device__ __forceinline__ float2 w16f(int n, int sgn){
    const float c[8]={1.f,0.92387953251f,0.70710678119f,0.38268343236f,0.f,-0.38268343236f,-0.70710678119f,-0.92387953251f};
    const float s[8]={0.f,0.38268343236f,0.70710678119f,0.92387953251f,1.f,0.92387953251f,0.70710678119f,0.38268343236f};
    return make_float2(c[n], sgn > 0 ? -s[n] : s[n]);
}

// In-register DFT16, DIF radix-2: natural-order input, slot s holds X[BR4[s]].
// SGN=+1 forward, SGN=-1 inverse (conjugate twiddles, unnormalized).
template<int SGN>
static __device__ __forceinline__ void dft16(float2 r[16])
{
    #pragma unroll
    for (int n = 0; n < 8; n++) {               // span 8, tw W16^n
        float2 a = r[n], b = r[n+8];
        r[n]   = cadd(a,b);
        r[n+8] = cmul(csub(a,b), w16f(n, SGN));
    }
    #pragma unroll
    for (int blk = 0; blk < 16; blk += 8)       // span 4, tw W8^n = W16^{2n}
        #pragma unroll
        for (int n = 0; n < 4; n++) {
            float2 a = r[blk+n], b = r[blk+n+4];
            r[blk+n]   = cadd(a,b);
            r[blk+n+4] = cmul(csub(a,b), w16f(2*n, SGN));
        }
    #pragma unroll
    for (int blk = 0; blk < 16; blk += 4) {     // span 2, tw {1, -+i}
        { float2 a = r[blk],   b = r[blk+2]; r[blk]   = cadd(a,b); r[blk+2] = csub(a,b); }
        { float2 a = r[blk+1], b = r[blk+3]; r[blk+1] = cadd(a,b);
          float2 d = csub(a,b); r[blk+3] = (SGN > 0) ? rot_mi(d) : rot_pi(d); }
    }
    #pragma unroll
    for (int blk = 0; blk < 16; blk += 2) {     // span 1
        float2 a = r[blk], b = r[blk+1];
        r[blk] = cadd(a,b); r[blk+1] = csub(a,b);
    }
}

// ---------------- init: twiddles + CSR of mtx/mtxi ----------------
__global__ void k_init(const float* __restrict__ mtx, const float* __restrict__ mtxi,
                       const float* __restrict__ gridz)
{
    int t = threadIdx.x;               // 512 threads
    if (t < 256) {
        float s, c;
        sincospif((float)t / 256.0f, &s, &c);
        d_W512[t] = make_float2(c, -s);
        sincospif((float)t / 128.0f, &s, &c);
        d_W256[t] = make_float2(c, -s);
    }
    int mat = t >> 8;
    int m   = t & 255;
    const float* M = mat ? mtxi : mtx;
    int cnt = 0;
    for (int k = 0; k < 256; k++) {
        float v = M[m*256 + k];
        if (v != 0.0f) {
            float g = 1.0f;
            if (mat == 0) { float z = gridz[k]; float z2 = z*z; g = z2*z2; }
            d_cols[mat][m][cnt] = k;
            d_vals[mat][m][cnt] = v * g;
            cnt++;
        }
    }
    d_cnt[mat][m] = cnt;
}

// ---------------- resampling (sparse row apply) ----------------
__global__ __launch_bounds__(256) void k_resample_fwd(const float* __restrict__ feature)
{
    int hw = blockIdx.x*256 + threadIdx.x;
    int m  = blockIdx.y;
    int bd = blockIdx.z;
    int n  = d_cnt[0][m];
    const float* inb = feature + (size_t)bd*T_DIM*HW2;
    float acc = 0.f;
    for (int j = 0; j < n; j++)
        acc += d_vals[0][m][j] * inb[(size_t)d_cols[0][m][j]*HW2 + hw];
    d_tmp[((size_t)(bd*T_DIM + m))*HW2 + hw] = acc;
}

__global__ __launch_bounds__(256) void k_resample_inv(float* __restrict__ out)
{
    int hw = blockIdx.x*256 + threadIdx.x;
    int m  = blockIdx.y;
    int bd = blockIdx.z;
    int n  = d_cnt[1][m];
    const float* inb = d_tmp + (size_t)bd*T_DIM*HW2;
    float acc = 0.f;
    for (int j = 0; j < n; j++)
        acc += d_vals[1][m][j] * inb[(size_t)d_cols[1][m][j]*HW2 + hw];
    out[((size_t)(bd*T_DIM + m))*HW2 + hw] = acc;
}

// ============ Pass A: W-axis forward R2C (128 real -> 256-pt -> keep 129) ============
// 8 lines/block; q fast in tid for coalescing. SMEM layout X[pos][line] padded.
__global__ __launch_bounds__(512) void k_fft_w_fwd()
{
    __shared__ float2 X[256][9];
    __shared__ float2 Wt[256];
    int tid = threadIdx.x;
    if (tid < 256) Wt[tid] = d_W512[tid];
    int ln = tid >> 6, q = tid & 63;
    size_t L = (size_t)blockIdx.x*8 + ln;
    const float* in = d_tmp + L*HW;
    #pragma unroll
    for (int k = 0; k < 2; k++) {                   // duplicate-fill (padded stage 1 free)
        int h = q + 64*k;
        float v = in[h];
        int p = brev8(h);
        X[p][ln]   = make_float2(v, 0.f);
        X[p+1][ln] = make_float2(v, 0.f);
    }
    __syncthreads();
    #pragma unroll
    for (int hi = 0; hi < 3; hi++) {                // radix-4 at h = 2, 8, 32
        const int h = 2 << (2*hi);
        int r = q & (h-1);
        int base = ((q & ~(h-1)) << 2) | r;
        float2 w1 = Wt[r*(256/h)];
        float2 w2 = Wt[r*(128/h)];
        float2 a0 = X[base][ln], a1 = X[base+h][ln], a2 = X[base+2*h][ln], a3 = X[base+3*h][ln];
        float2 t1 = cmul(a1, w1), t3 = cmul(a3, w1);
        float2 b0 = cadd(a0,t1), b1 = csub(a0,t1);
        float2 b2 = cadd(a2,t3), b3 = csub(a2,t3);
        float2 u2 = cmul(b2, w2), u3 = rot_mi(cmul(b3, w2));
        X[base][ln]     = cadd(b0,u2);
        X[base+2*h][ln] = csub(b0,u2);
        X[base+h][ln]   = cadd(b1,u3);
        X[base+3*h][ln] = csub(b1,u3);
        __syncthreads();
    }
    #pragma unroll
    for (int k = 0; k < 2; k++) {                   // radix-2 at h = 128
        int j = q + 64*k;
        float2 w = Wt[2*j];
        float2 a = X[j][ln], c = cmul(X[j+128][ln], w);
        X[j][ln] = cadd(a,c); X[j+128][ln] = csub(a,c);
    }
    __syncthreads();
    float2* out = d_bufA + L*KWS;
    out[q]    = X[q][ln];
    out[q+64] = X[q+64][ln];
    if (q == 0) out[128] = X[128][ln];
}

// ============ Pass B: H-axis forward (128 -> 256, four-step 16x16 register FFT) ============
// 256 threads: kwl = tid&15, n1 = tid>>4. One (bd,m) row-block, 16 kw columns.
__global__ __launch_bounds__(256) void k_fft_h_fwd()
{
    __shared__ float2 Xs[16][17][17];   // [k2][n1][kwl]
    __shared__ float2 Wtw[256];         // W256
    int tid = threadIdx.x;
    Wtw[tid] = d_W256[tid];
    int kwl = tid & 15, n1 = tid >> 4;
    int kw = blockIdx.x*16 + kwl;
    bool ok = kw < KW;
    const float2* in = d_bufA + ((size_t)(blockIdx.z*T_DIM + blockIdx.y))*HW*KWS;
    float2 r[16];
    #pragma unroll
    for (int n2 = 0; n2 < 8; n2++)
        r[n2] = ok ? in[(n1 + 16*n2)*KWS + kw] : make_float2(0.f,0.f);
    #pragma unroll
    for (int n2 = 8; n2 < 16; n2++) r[n2] = make_float2(0.f,0.f);
    __syncthreads();                    // Wtw ready
    dft16<1>(r);                        // over n2 -> k2 (bitrev slots)
    #pragma unroll
    for (int s = 0; s < 16; s++) {
        int k2 = BR4[s];
        Xs[k2][n1][kwl] = cmul(r[s], Wtw[n1*k2]);   // twiddle W256^{n1*k2}
    }
    __syncthreads();
    int k2p = n1;                       // thread now owns k2 = tid>>4
    #pragma unroll
    for (int j = 0; j < 16; j++) r[j] = Xs[k2p][j][kwl];
    dft16<1>(r);                        // over n1 -> k1 (bitrev slots)
    float2* out = d_bufB + ((size_t)(blockIdx.z*T_DIM + blockIdx.y))*T_DIM*KWS;
    if (ok) {
        #pragma unroll
        for (int s = 0; s < 16; s++) {
            int kh = k2p + 16*BR4[s];
            out[kh*KWS + kw] = r[s];
        }
    }
}

// ============ Pass C: T-axis fwd(256->512) * invpsf * inv, both bd fused ============
// cols: 8 = 2 bd x 4 kw; both bd share the same psf sectors.
__global__ __launch_bounds__(512) void k_fft_t(const float* __restrict__ pr, const float* __restrict__ pi)
{
    __shared__ float2 X[512][9];
    __shared__ float2 Wt[256];
    int tid = threadIdx.x;
    if (tid < 256) Wt[tid] = d_W512[tid];
    int kw0 = blockIdx.x * 4;
    int kh  = blockIdx.y;
    const int TSTR = T_DIM*KWS;
    float2* base0 = d_bufB + (size_t)kh*KWS;
    const size_t BDSTR = (size_t)T_DIM*T_DIM*KWS;
    #pragma unroll
    for (int it = 0; it < 4; it++) {                // dup-fill 256 real t-rows
        int idx = tid + it*512;
        int t = idx >> 3, col = idx & 7;
        int bd = col >> 2, kw = kw0 + (col & 3);
        float2 v = make_float2(0.f, 0.f);
        if (kw < KW) v = base0[(size_t)bd*BDSTR + (size_t)t*TSTR + kw];
        int p = brev9(t);
        X[p][col] = v; X[p+1][col] = v;
    }
    __syncthreads();
    #pragma unroll
    for (int hi = 0; hi < 4; hi++) {                // fwd radix-4 at h = 2, 8, 32, 128
        const int h = 2 << (2*hi);
        #pragma unroll
        for (int it = 0; it < 2; it++) {
            int b = tid + it*512;
            int col = b & 7, q = b >> 3;            // q in [0,128)
            int r = q & (h-1);
            int bs = ((q & ~(h-1)) << 2) | r;
            float2 w1 = Wt[r*(256/h)];
            float2 w2 = Wt[r*(128/h)];
            float2 a0 = X[bs][col], a1 = X[bs+h][col], a2 = X[bs+2*h][col], a3 = X[bs+3*h][col];
            float2 t1 = cmul(a1, w1), t3 = cmul(a3, w1);
            float2 b0 = cadd(a0,t1), b1 = csub(a0,t1);
            float2 b2 = cadd(a2,t3), b3 = csub(a2,t3);
            float2 u2 = cmul(b2, w2), u3 = rot_mi(cmul(b3, w2));
            X[bs][col]     = cadd(b0,u2);
            X[bs+2*h][col] = csub(b0,u2);
            X[bs+h][col]   = cadd(b1,u3);
            X[bs+3*h][col] = csub(b1,u3);
        }
        __syncthreads();
    }
    const float NORM = 1.0f / 33554432.0f;
    #pragma unroll
    for (int it = 0; it < 8; it++) {                // Wiener multiply (psf shared by both bd)
        int idx = tid + it*512;
        int kt = idx >> 3, col = idx & 7, kw = kw0 + (col & 3);
        if (kw < KW) {
            size_t o = ((size_t)kt*256 + kh)*256 + kw;
            float2 p = make_float2(pr[o]*NORM, pi[o]*NORM);
            X[kt][col] = cmul(X[kt][col], p);
        }
    }
    __syncthreads();
    #pragma unroll
    for (int hi = 0; hi < 4; hi++) {                // inverse DIF radix-4: H = 256, 64, 16, 4
        const int H = 256 >> (2*hi);
        const int Hh = H >> 1;
        #pragma unroll
        for (int it = 0; it < 2; it++) {
            int b = tid + it*512;
            int col = b & 7, q = b >> 3;
            int r = q & (Hh-1);
            int bs = ((q & ~(Hh-1)) << 2) | r;
            float2 w1 = Wt[r*(256/H)];  w1.y = -w1.y;
            float2 wh = Wt[r*(512/H)];  wh.y = -wh.y;
            float2 e0 = X[bs][col], e1 = X[bs+Hh][col], e2 = X[bs+H][col], e3 = X[bs+H+Hh][col];
            float2 b0 = cadd(e0,e2);
            float2 b2 = cmul(csub(e0,e2), w1);
            float2 b1 = cadd(e1,e3);
            float2 b3 = rot_pi(cmul(csub(e1,e3), w1));
            X[bs][col]      = cadd(b0,b1);
            X[bs+Hh][col]   = cmul(csub(b0,b1), wh);
            X[bs+H][col]    = cadd(b2,b3);
            X[bs+H+Hh][col] = cmul(csub(b2,b3), wh);
        }
        __syncthreads();
    }
    #pragma unroll
    for (int it = 0; it < 4; it++) {                // final inverse radix-2 (w = 1)
        int b = tid + it*512;
        int col = b & 7, j = b >> 3;                // j in [0,256)
        float2 a = X[2*j][col], c = X[2*j+1][col];
        X[2*j][col] = cadd(a,c); X[2*j+1][col] = csub(a,c);
    }
    __syncthreads();
    #pragma unroll
    for (int it = 0; it < 4; it++) {                // crop t<256, undo bitrev
        int idx = tid + it*512;
        int t = idx >> 3, col = idx & 7;
        int bd = col >> 2, kw = kw0 + (col & 3);
        if (kw < KW) base0[(size_t)bd*BDSTR + (size_t)t*TSTR + kw] = X[brev9(t)][col];
    }
}

// ============ Pass D: H-axis inverse (256 -> crop 128, four-step 16x16 register FFT) ============
__global__ __launch_bounds__(256) void k_fft_h_inv()
{
    __shared__ float2 Xs[16][17][17];   // [n1][k2][kwl]
    __shared__ float2 Wtw[256];
    int tid = threadIdx.x;
    Wtw[tid] = d_W256[tid];
    int kwl = tid & 15, k2 = tid >> 4;
    int kw = blockIdx.x*16 + kwl;
    bool ok = kw < KW;
    const float2* in = d_bufB + ((size_t)(blockIdx.z*T_DIM + blockIdx.y))*T_DIM*KWS;
    float2 r[16];
    #pragma unroll
    for (int k1 = 0; k1 < 16; k1++)
        r[k1] = ok ? in[(k2 + 16*k1)*KWS + kw] : make_float2(0.f,0.f);
    __syncthreads();                    // Wtw ready
    dft16<-1>(r);                       // over k1 -> n1 (bitrev slots)
    #pragma unroll
    for (int s = 0; s < 16; s++) {
        int n1 = BR4[s];
        Xs[n1][k2][kwl] = cmulc(r[s], Wtw[n1*k2]);  // conj twiddle
    }
    __syncthreads();
    int n1p = k2;                       // thread now owns n1
    #pragma unroll
    for (int j = 0; j < 16; j++) r[j] = Xs[n1p][j][kwl];
    dft16<-1>(r);                       // over k2 -> n2 (bitrev slots)
    float2* out = d_bufA + ((size_t)(blockIdx.z*T_DIM + blockIdx.y))*HW*KWS;
    if (ok) {
        #pragma unroll
        for (int s = 0; s < 16; s++) {
            int n2 = BR4[s];
            if (n2 < 8) out[(n1p + 16*n2)*KWS + kw] = r[s];   // crop h < 128
        }
    }
}

// ============ Pass E: W-axis inverse C2R (Hermitian 129 -> 256 -> real crop 128) ============
__global__ __launch_bounds__(512) void k_fft_w_inv()
{
    __shared__ float2 X[256][9];
    __shared__ float2 Wt[256];
    int tid = threadIdx.x;
    if (tid < 256) Wt[tid] = d_W512[tid];
    int ln = tid >> 6, q = tid & 63;
    size_t L = (size_t)blockIdx.x*8 + ln;
    const float2* in = d_bufA + L*KWS;
    #pragma unroll
    for (int k = 0; k < 4; k++) {
        int e = q + 64*k;
        float2 v;
        if (e <= 128) v = in[e];
        else { float2 c = in[256-e]; v = make_float2(c.x, -c.y); }
        X[brev8(e)][ln] = v;
    }
    __syncthreads();
    #pragma unroll
    for (int hi = 0; hi < 4; hi++) {                // inverse radix-4 at h = 1, 4, 16, 64
        const int h = 1 << (2*hi);
        int r = q & (h-1);
        int bs = ((q & ~(h-1)) << 2) | r;
        float2 w1 = Wt[r*(256/h)];  w1.y = -w1.y;
        float2 w2 = Wt[r*(128/h)];  w2.y = -w2.y;
        float2 a0 = X[bs][ln], a1 = X[bs+h][ln], a2 = X[bs+2*h][ln], a3 = X[bs+3*h][ln];
        float2 t1 = cmul(a1, w1), t3 = cmul(a3, w1);
        float2 b0 = cadd(a0,t1), b1 = csub(a0,t1);
        float2 b2 = cadd(a2,t3), b3 = csub(a2,t3);
        float2 u2 = cmul(b2, w2), u3 = rot_pi(cmul(b3, w2));
        X[bs][ln]     = cadd(b0,u2);
        X[bs+2*h][ln] = csub(b0,u2);
        X[bs+h][ln]   = cadd(b1,u3);
        X[bs+3*h][ln] = csub(b1,u3);
        __syncthreads();
    }
    float* out = d_tmp + L*HW;
    out[q]      = X[q][ln].x;
    out[q + 64] = X[q + 64][ln].x;
}

// ---------------- launch ----------------
extern "C" void kernel_launch(void* const* d_in, const int* in_sizes, int n_in,
                              void* d_out, int out_size)
{
    (void)in_sizes; (void)n_in; (void)out_size;
    const float* feature = (const float*)d_in[0];
    const float* gridz   = (const float*)d_in[1];
    const float* mtx     = (const float*)d_in[2];
    const float* mtxi    = (const float*)d_in[3];
    const float* pr      = (const float*)d_in[4];
    const float* pi      = (const float*)d_in[5];
    float* out = (float*)d_out;

    k_init<<<1, 512>>>(mtx, mtxi, gridz);

    k_resample_fwd<<<dim3(HW2/256, 256, BD), 256>>>(feature);

    k_fft_w_fwd<<<(BD*T_DIM*HW)/8, 512>>>();

    k_fft_h_fwd<<<dim3((KW + 15)/16, T_DIM, BD), 256>>>();

    k_fft_t<<<dim3((KW + 3)/4, T_DIM), 512>>>(pr, pi);       // 33 x 256

    k_fft_h_inv<<<dim3((KW + 15)/16, T_DIM, BD), 256>>>();

    k_fft_w_inv<<<(BD*T_DIM*HW)/8, 512>>>();

    k_resample_inv<<<dim3(HW2/256, 256, BD), 256>>>(out);
}

// round 4
// speedup vs baseline: 1.4545x; 1.4545x over previous
#include <cuda_runtime.h>
#include <cstdint>

// ---------------- problem dims ----------------
#define T_DIM 256
#define HW    128
#define HW2   (HW*HW)
#define KW    129      // half-spectrum bins along W (Hermitian)
#define KWS   132      // padded row stride (float2)
#define BD    2

// ---------------- device scratch ----------------
__device__ static float  d_tmp [(size_t)BD*T_DIM*HW*HW];     // vol (w_inv out)
__device__ static float2 d_bufA[(size_t)BD*T_DIM*HW*KWS];
__device__ static float2 d_bufB[(size_t)BD*T_DIM*T_DIM*KWS];
__device__ static float2 d_W512[256];                       // exp(-2*pi*i*k/512)
__device__ static float2 d_W256[256];                       // exp(-2*pi*i*k/256)
__device__ static int    d_cols[2][256][256];
__device__ static float  d_vals[2][256][256];
__device__ static int    d_cnt [2][256];

// ---------------- complex helpers ----------------
static __device__ __forceinline__ float2 cadd(float2 a, float2 b){ return make_float2(a.x+b.x, a.y+b.y); }
static __device__ __forceinline__ float2 csub(float2 a, float2 b){ return make_float2(a.x-b.x, a.y-b.y); }
static __device__ __forceinline__ float2 cmul(float2 a, float2 b){ return make_float2(a.x*b.x - a.y*b.y, a.x*b.y + a.y*b.x); }
static __device__ __forceinline__ float2 cmulc(float2 a, float2 b){ return make_float2(a.x*b.x + a.y*b.y, a.y*b.x - a.x*b.y); } // a*conj(b)
static __device__ __forceinline__ float2 rot_mi(float2 a){ return make_float2(a.y, -a.x); }
static __device__ __forceinline__ float2 rot_pi(float2 a){ return make_float2(-a.y, a.x); }

static __device__ __forceinline__ int brev9(int i){ return __brev((unsigned)i) >> 23; }
static __device__ __forceinline__ constexpr int br4(int s){
    return ((s&1)<<3) | ((s&2)<<1) | ((s&4)>>1) | ((s&8)>>3);
}

// W16^n = exp(-2*pi*i*n/16), n=0..7 (hardcoded)
static __device__ __forceinline__ float2 w16f(int n, int sgn){
    const float c[8]={1.f,0.92387953251f,0.70710678119f,0.38268343236f,0.f,-0.38268343236f,-0.70710678119f,-0.92387953251f};
    const float s[8]={0.f,0.38268343236f,0.70710678119f,0.92387953251f,1.f,0.92387953251f,0.70710678119f,0.38268343236f};
    return make_float2(c[n], sgn > 0 ? -s[n] : s[n]);
}

// In-register DFT16, DIF: natural-order input, slot s holds X[br4(s)].
template<int SGN>
static __device__ __forceinline__ void dft16(float2 r[16])
{
    #pragma unroll
    for (int n = 0; n < 8; n++) {
        float2 a = r[n], b = r[n+8];
        r[n]   = cadd(a,b);
        r[n+8] = cmul(csub(a,b), w16f(n, SGN));
    }
    #pragma unroll
    for (int blk = 0; blk < 16; blk += 8)
        #pragma unroll
        for (int n = 0; n < 4; n++) {
            float2 a = r[blk+n], b = r[blk+n+4];
            r[blk+n]   = cadd(a,b);
            r[blk+n+4] = cmul(csub(a,b), w16f(2*n, SGN));
        }
    #pragma unroll
    for (int blk = 0; blk < 16; blk += 4) {
        { float2 a = r[blk],   b = r[blk+2]; r[blk]   = cadd(a,b); r[blk+2] = csub(a,b); }
        { float2 a = r[blk+1], b = r[blk+3]; r[blk+1] = cadd(a,b);
          float2 d = csub(a,b); r[blk+3] = (SGN > 0) ? rot_mi(d) : rot_pi(d); }
    }
    #pragma unroll
    for (int blk = 0; blk < 16; blk += 2) {
        float2 a = r[blk], b = r[blk+1];
        r[blk] = cadd(a,b); r[blk+1] = csub(a,b);
    }
}

// ---------------- init: twiddles + CSR of mtx/mtxi ----------------
__global__ void k_init(const float* __restrict__ mtx, const float* __restrict__ mtxi,
                       const float* __restrict__ gridz)
{
    int t = threadIdx.x;               // 512 threads
    if (t < 256) {
        float s, c;
        sincospif((float)t / 256.0f, &s, &c);
        d_W512[t] = make_float2(c, -s);
        sincospif((float)t / 128.0f, &s, &c);
        d_W256[t] = make_float2(c, -s);
    }
    int mat = t >> 8;
    int m   = t & 255;
    const float* M = mat ? mtxi : mtx;
    int cnt = 0;
    for (int k = 0; k < 256; k++) {
        float v = M[m*256 + k];
        if (v != 0.0f) {
            float g = 1.0f;
            if (mat == 0) { float z = gridz[k]; float z2 = z*z; g = z2*z2; }
            d_cols[mat][m][cnt] = k;
            d_vals[mat][m][cnt] = v * g;
            cnt++;
        }
    }
    d_cnt[mat][m] = cnt;
}

// ---------------- inverse resampling (sparse row apply on vol in d_tmp) ----------------
__global__ __launch_bounds__(256) void k_resample_inv(float* __restrict__ out)
{
    int hw = blockIdx.x*256 + threadIdx.x;
    int m  = blockIdx.y;
    int bd = blockIdx.z;
    int n  = d_cnt[1][m];
    const float* inb = d_tmp + (size_t)bd*T_DIM*HW2;
    float acc = 0.f;
    for (int j = 0; j < n; j++)
        acc += d_vals[1][m][j] * inb[(size_t)d_cols[1][m][j]*HW2 + hw];
    out[((size_t)(bd*T_DIM + m))*HW2 + hw] = acc;
}

// ============ Pass A: fused resample + W-axis forward (128 real -> 256-pt, keep 129) ============
// 16 lines/block, 16 threads/line. Four-step 16x16 register FFT.
__global__ __launch_bounds__(256) void k_fft_w_fwd(const float* __restrict__ feature)
{
    __shared__ float2 Xs[16][16][17];   // [line][k2][n1 + pad]
    __shared__ float2 Wtw[256];
    int tid = threadIdx.x;
    Wtw[tid] = d_W256[tid];
    int n1 = tid & 15, ln = tid >> 4;
    int G  = blockIdx.x*16 + ln;        // (bd*256 + m)*128 + h
    int h  = G & 127;
    int m  = (G >> 7) & 255;
    int bd = G >> 15;
    int nnz = d_cnt[0][m];
    float acc[8];
    #pragma unroll
    for (int i = 0; i < 8; i++) acc[i] = 0.f;
    for (int j = 0; j < nnz; j++) {
        float v = d_vals[0][m][j];
        const float* fp = feature + (((size_t)(bd*T_DIM + d_cols[0][m][j]))*HW + h)*HW;
        #pragma unroll
        for (int n2 = 0; n2 < 8; n2++) acc[n2] += v * fp[n1 + 16*n2];
    }
    float2 r[16];
    #pragma unroll
    for (int n2 = 0; n2 < 8; n2++)  r[n2] = make_float2(acc[n2], 0.f);
    #pragma unroll
    for (int n2 = 8; n2 < 16; n2++) r[n2] = make_float2(0.f, 0.f);
    __syncthreads();                    // Wtw ready
    dft16<1>(r);                        // over n2 -> k2 (bitrev slots)
    #pragma unroll
    for (int s = 0; s < 16; s++) {
        const int k2 = br4(s);
        Xs[ln][k2][n1] = cmul(r[s], Wtw[n1*k2]);
    }
    __syncthreads();
    int k2p = n1;
    #pragma unroll
    for (int j = 0; j < 16; j++) r[j] = Xs[ln][k2p][j];
    dft16<1>(r);                        // over n1 -> k1 (bitrev slots)
    float2* out = d_bufA + (size_t)G*KWS;
    #pragma unroll
    for (int s = 0; s < 16; s++) {
        const int k1 = br4(s);
        int k = k2p + 16*k1;
        if (k <= 128) out[k] = r[s];
    }
}

// ============ Pass B: H-axis forward (128 -> 256, four-step 16x16 register FFT) ============
__global__ __launch_bounds__(256) void k_fft_h_fwd()
{
    __shared__ float2 Xs[16][17][17];   // [k2][n1][kwl]
    __shared__ float2 Wtw[256];
    int tid = threadIdx.x;
    Wtw[tid] = d_W256[tid];
    int kwl = tid & 15, n1 = tid >> 4;
    int kw = blockIdx.x*16 + kwl;
    bool ok = kw < KW;
    const float2* in = d_bufA + ((size_t)(blockIdx.z*T_DIM + blockIdx.y))*HW*KWS;
    float2 r[16];
    #pragma unroll
    for (int n2 = 0; n2 < 8; n2++)
        r[n2] = ok ? in[(n1 + 16*n2)*KWS + kw] : make_float2(0.f,0.f);
    #pragma unroll
    for (int n2 = 8; n2 < 16; n2++) r[n2] = make_float2(0.f,0.f);
    __syncthreads();
    dft16<1>(r);
    #pragma unroll
    for (int s = 0; s < 16; s++) {
        const int k2 = br4(s);
        Xs[k2][n1][kwl] = cmul(r[s], Wtw[n1*k2]);
    }
    __syncthreads();
    int k2p = n1;
    #pragma unroll
    for (int j = 0; j < 16; j++) r[j] = Xs[k2p][j][kwl];
    dft16<1>(r);
    float2* out = d_bufB + ((size_t)(blockIdx.z*T_DIM + blockIdx.y))*T_DIM*KWS;
    if (ok) {
        #pragma unroll
        for (int s = 0; s < 16; s++) {
            int kh = k2p + 16*br4(s);
            out[kh*KWS + kw] = r[s];
        }
    }
}

// ============ Pass C: T-axis fwd(256->512) * invpsf * inv, both bd fused ============
__global__ __launch_bounds__(512) void k_fft_t(const float* __restrict__ pr, const float* __restrict__ pi)
{
    __shared__ float2 X[512][9];
    __shared__ float2 Wt[256];
    int tid = threadIdx.x;
    if (tid < 256) Wt[tid] = d_W512[tid];
    int kw0 = blockIdx.x * 4;
    int kh  = blockIdx.y;
    const int TSTR = T_DIM*KWS;
    float2* base0 = d_bufB + (size_t)kh*KWS;
    const size_t BDSTR = (size_t)T_DIM*T_DIM*KWS;
    #pragma unroll
    for (int it = 0; it < 4; it++) {
        int idx = tid + it*512;
        int t = idx >> 3, col = idx & 7;
        int bd = col >> 2, kw = kw0 + (col & 3);
        float2 v = make_float2(0.f, 0.f);
        if (kw < KW) v = base0[(size_t)bd*BDSTR + (size_t)t*TSTR + kw];
        int p = brev9(t);
        X[p][col] = v; X[p+1][col] = v;
    }
    __syncthreads();
    #pragma unroll
    for (int hi = 0; hi < 4; hi++) {
        const int h = 2 << (2*hi);
        #pragma unroll
        for (int it = 0; it < 2; it++) {
            int b = tid + it*512;
            int col = b & 7, q = b >> 3;
            int r = q & (h-1);
            int bs = ((q & ~(h-1)) << 2) | r;
            float2 w1 = Wt[r*(256/h)];
            float2 w2 = Wt[r*(128/h)];
            float2 a0 = X[bs][col], a1 = X[bs+h][col], a2 = X[bs+2*h][col], a3 = X[bs+3*h][col];
            float2 t1 = cmul(a1, w1), t3 = cmul(a3, w1);
            float2 b0 = cadd(a0,t1), b1 = csub(a0,t1);
            float2 b2 = cadd(a2,t3), b3 = csub(a2,t3);
            float2 u2 = cmul(b2, w2), u3 = rot_mi(cmul(b3, w2));
            X[bs][col]     = cadd(b0,u2);
            X[bs+2*h][col] = csub(b0,u2);
            X[bs+h][col]   = cadd(b1,u3);
            X[bs+3*h][col] = csub(b1,u3);
        }
        __syncthreads();
    }
    const float NORM = 1.0f / 33554432.0f;
    #pragma unroll
    for (int it = 0; it < 8; it++) {
        int idx = tid + it*512;
        int kt = idx >> 3, col = idx & 7, kw = kw0 + (col & 3);
        if (kw < KW) {
            size_t o = ((size_t)kt*256 + kh)*256 + kw;
            float2 p = make_float2(pr[o]*NORM, pi[o]*NORM);
            X[kt][col] = cmul(X[kt][col], p);
        }
    }
    __syncthreads();
    #pragma unroll
    for (int hi = 0; hi < 4; hi++) {
        const int H = 256 >> (2*hi);
        const int Hh = H >> 1;
        #pragma unroll
        for (int it = 0; it < 2; it++) {
            int b = tid + it*512;
            int col = b & 7, q = b >> 3;
            int r = q & (Hh-1);
            int bs = ((q & ~(Hh-1)) << 2) | r;
            float2 w1 = Wt[r*(256/H)];  w1.y = -w1.y;
            float2 wh = Wt[r*(512/H)];  wh.y = -wh.y;
            float2 e0 = X[bs][col], e1 = X[bs+Hh][col], e2 = X[bs+H][col], e3 = X[bs+H+Hh][col];
            float2 b0 = cadd(e0,e2);
            float2 b2 = cmul(csub(e0,e2), w1);
            float2 b1 = cadd(e1,e3);
            float2 b3 = rot_pi(cmul(csub(e1,e3), w1));
            X[bs][col]      = cadd(b0,b1);
            X[bs+Hh][col]   = cmul(csub(b0,b1), wh);
            X[bs+H][col]    = cadd(b2,b3);
            X[bs+H+Hh][col] = cmul(csub(b2,b3), wh);
        }
        __syncthreads();
    }
    #pragma unroll
    for (int it = 0; it < 4; it++) {
        int b = tid + it*512;
        int col = b & 7, j = b >> 3;
        float2 a = X[2*j][col], c = X[2*j+1][col];
        X[2*j][col] = cadd(a,c); X[2*j+1][col] = csub(a,c);
    }
    __syncthreads();
    #pragma unroll
    for (int it = 0; it < 4; it++) {
        int idx = tid + it*512;
        int t = idx >> 3, col = idx & 7;
        int bd = col >> 2, kw = kw0 + (col & 3);
        if (kw < KW) base0[(size_t)bd*BDSTR + (size_t)t*TSTR + kw] = X[brev9(t)][col];
    }
}

// ============ Pass D: H-axis inverse (256 -> crop 128, four-step) ============
__global__ __launch_bounds__(256) void k_fft_h_inv()
{
    __shared__ float2 Xs[16][17][17];   // [n1][k2][kwl]
    __shared__ float2 Wtw[256];
    int tid = threadIdx.x;
    Wtw[tid] = d_W256[tid];
    int kwl = tid & 15, k2 = tid >> 4;
    int kw = blockIdx.x*16 + kwl;
    bool ok = kw < KW;
    const float2* in = d_bufB + ((size_t)(blockIdx.z*T_DIM + blockIdx.y))*T_DIM*KWS;
    float2 r[16];
    #pragma unroll
    for (int k1 = 0; k1 < 16; k1++)
        r[k1] = ok ? in[(k2 + 16*k1)*KWS + kw] : make_float2(0.f,0.f);
    __syncthreads();
    dft16<-1>(r);
    #pragma unroll
    for (int s = 0; s < 16; s++) {
        const int n1 = br4(s);
        Xs[n1][k2][kwl] = cmulc(r[s], Wtw[n1*k2]);
    }
    __syncthreads();
    int n1p = k2;
    #pragma unroll
    for (int j = 0; j < 16; j++) r[j] = Xs[n1p][j][kwl];
    dft16<-1>(r);
    float2* out = d_bufA + ((size_t)(blockIdx.z*T_DIM + blockIdx.y))*HW*KWS;
    if (ok) {
        #pragma unroll
        for (int s = 0; s < 16; s++) {
            const int n2 = br4(s);
            if (n2 < 8) out[(n1p + 16*n2)*KWS + kw] = r[s];
        }
    }
}

// ============ Pass E: W-axis inverse C2R (Hermitian 129 -> 256 -> real 128, four-step) ============
__global__ __launch_bounds__(256) void k_fft_w_inv()
{
    __shared__ float2 Xs[16][16][17];   // [line][n1][k2 + pad]
    __shared__ float2 Wtw[256];
    int tid = threadIdx.x;
    Wtw[tid] = d_W256[tid];
    int tt = tid & 15, ln = tid >> 4;   // tt owns k2 in step 1
    size_t G = (size_t)blockIdx.x*16 + ln;   // (bd*256 + t)*128 + h
    const float2* in = d_bufA + G*KWS;
    float2 r[16];
    #pragma unroll
    for (int k1 = 0; k1 < 16; k1++) {
        int k = tt + 16*k1;
        float2 v;
        if (k <= 128) v = in[k];
        else { float2 c = in[256-k]; v = make_float2(c.x, -c.y); }
        r[k1] = v;
    }
    __syncthreads();
    dft16<-1>(r);                        // over k1 -> n1 (bitrev slots)
    #pragma unroll
    for (int s = 0; s < 16; s++) {
        const int n1 = br4(s);
        Xs[ln][n1][tt] = cmulc(r[s], Wtw[n1*tt]);
    }
    __syncthreads();
    int n1p = tt;
    #pragma unroll
    for (int j = 0; j < 16; j++) r[j] = Xs[ln][n1p][j];
    dft16<-1>(r);                        // over k2 -> n2 (bitrev slots)
    float* outp = d_tmp + G*HW;
    #pragma unroll
    for (int s = 0; s < 16; s++) {
        const int n2 = br4(s);
        if (n2 < 8) outp[n1p + 16*n2] = r[s].x;   // crop w < 128, real part
    }
}

// ---------------- launch ----------------
extern "C" void kernel_launch(void* const* d_in, const int* in_sizes, int n_in,
                              void* d_out, int out_size)
{
    (void)in_sizes; (void)n_in; (void)out_size;
    const float* feature = (const float*)d_in[0];
    const float* gridz   = (const float*)d_in[1];
    const float* mtx     = (const float*)d_in[2];
    const float* mtxi    = (const float*)d_in[3];
    const float* pr      = (const float*)d_in[4];
    const float* pi      = (const float*)d_in[5];
    float* out = (float*)d_out;

    k_init<<<1, 512>>>(mtx, mtxi, gridz);

    k_fft_w_fwd<<<(BD*T_DIM*HW)/16, 256>>>(feature);         // fused resample + W FFT

    k_fft_h_fwd<<<dim3((KW + 15)/16, T_DIM, BD), 256>>>();

    k_fft_t<<<dim3((KW + 3)/4, T_DIM), 512>>>(pr, pi);

    k_fft_h_inv<<<dim3((KW + 15)/16, T_DIM, BD), 256>>>();

    k_fft_w_inv<<<(BD*T_DIM*HW)/16, 256>>>();

    k_resample_inv<<<dim3(HW2/256, 256, BD), 256>>>(out);
}

// round 5
// speedup vs baseline: 2.4703x; 1.6983x over previous
#include <cuda_runtime.h>
#include <cstdint>

// ---------------- problem dims ----------------
#define T_DIM 256
#define HW    128
#define HW2   (HW*HW)
#define KW    129      // half-spectrum bins along W (Hermitian)
#define KWS   132      // padded row stride (float2)
#define BD    2

// ---------------- device scratch ----------------
__device__ static float  d_tmp [(size_t)BD*T_DIM*HW*HW];     // vol (w_inv out)
__device__ static float2 d_bufA[(size_t)BD*T_DIM*HW*KWS];
__device__ static float2 d_bufB[(size_t)BD*T_DIM*T_DIM*KWS];
__device__ static float2 d_W512[256];                       // exp(-2*pi*i*k/512), k<256
__device__ static float2 d_W256[256];                       // exp(-2*pi*i*k/256)
__device__ static int    d_cols[2][256][256];
__device__ static float  d_vals[2][256][256];
__device__ static int    d_cnt [2][256];

// ---------------- complex helpers ----------------
static __device__ __forceinline__ float2 cadd(float2 a, float2 b){ return make_float2(a.x+b.x, a.y+b.y); }
static __device__ __forceinline__ float2 csub(float2 a, float2 b){ return make_float2(a.x-b.x, a.y-b.y); }
static __device__ __forceinline__ float2 cmul(float2 a, float2 b){ return make_float2(a.x*b.x - a.y*b.y, a.x*b.y + a.y*b.x); }
static __device__ __forceinline__ float2 cmulc(float2 a, float2 b){ return make_float2(a.x*b.x + a.y*b.y, a.y*b.x - a.x*b.y); } // a*conj(b)
static __device__ __forceinline__ float2 rot_mi(float2 a){ return make_float2(a.y, -a.x); }
static __device__ __forceinline__ float2 rot_pi(float2 a){ return make_float2(-a.y, a.x); }

static __device__ __forceinline__ constexpr int br4(int s){
    return ((s&1)<<3) | ((s&2)<<1) | ((s&4)>>1) | ((s&8)>>3);
}

// W16^n = exp(-2*pi*i*n/16), n=0..7 (hardcoded)
static __device__ __forceinline__ float2 w16f(int n, int sgn){
    const float c[8]={1.f,0.92387953251f,0.70710678119f,0.38268343236f,0.f,-0.38268343236f,-0.70710678119f,-0.92387953251f};
    const float s[8]={0.f,0.38268343236f,0.70710678119f,0.92387953251f,1.f,0.92387953251f,0.70710678119f,0.38268343236f};
    return make_float2(c[n], sgn > 0 ? -s[n] : s[n]);
}

// In-register DFT16, DIF: natural-order input, slot s holds X[br4(s)].
template<int SGN>
static __device__ __forceinline__ void dft16(float2 r[16])
{
    #pragma unroll
    for (int n = 0; n < 8; n++) {
        float2 a = r[n], b = r[n+8];
        r[n]   = cadd(a,b);
        r[n+8] = cmul(csub(a,b), w16f(n, SGN));
    }
    #pragma unroll
    for (int blk = 0; blk < 16; blk += 8)
        #pragma unroll
        for (int n = 0; n < 4; n++) {
            float2 a = r[blk+n], b = r[blk+n+4];
            r[blk+n]   = cadd(a,b);
            r[blk+n+4] = cmul(csub(a,b), w16f(2*n, SGN));
        }
    #pragma unroll
    for (int blk = 0; blk < 16; blk += 4) {
        { float2 a = r[blk],   b = r[blk+2]; r[blk]   = cadd(a,b); r[blk+2] = csub(a,b); }
        { float2 a = r[blk+1], b = r[blk+3]; r[blk+1] = cadd(a,b);
          float2 d = csub(a,b); r[blk+3] = (SGN > 0) ? rot_mi(d) : rot_pi(d); }
    }
    #pragma unroll
    for (int blk = 0; blk < 16; blk += 2) {
        float2 a = r[blk], b = r[blk+1];
        r[blk] = cadd(a,b); r[blk+1] = csub(a,b);
    }
}

// ---------------- init: twiddles + CSR of mtx/mtxi ----------------
__global__ void k_init(const float* __restrict__ mtx, const float* __restrict__ mtxi,
                       const float* __restrict__ gridz)
{
    int t = threadIdx.x;               // 512 threads
    if (t < 256) {
        float s, c;
        sincospif((float)t / 256.0f, &s, &c);
        d_W512[t] = make_float2(c, -s);
        sincospif((float)t / 128.0f, &s, &c);
        d_W256[t] = make_float2(c, -s);
    }
    int mat = t >> 8;
    int m   = t & 255;
    const float* M = mat ? mtxi : mtx;
    int cnt = 0;
    for (int k = 0; k < 256; k++) {
        float v = M[m*256 + k];
        if (v != 0.0f) {
            float g = 1.0f;
            if (mat == 0) { float z = gridz[k]; float z2 = z*z; g = z2*z2; }
            d_cols[mat][m][cnt] = k;
            d_vals[mat][m][cnt] = v * g;
            cnt++;
        }
    }
    d_cnt[mat][m] = cnt;
}

// ---------------- inverse resampling (sparse row apply on vol in d_tmp) ----------------
__global__ __launch_bounds__(256) void k_resample_inv(float* __restrict__ out)
{
    int hw = blockIdx.x*256 + threadIdx.x;
    int m  = blockIdx.y;
    int bd = blockIdx.z;
    int n  = d_cnt[1][m];
    const float* inb = d_tmp + (size_t)bd*T_DIM*HW2;
    float acc = 0.f;
    for (int j = 0; j < n; j++)
        acc += d_vals[1][m][j] * inb[(size_t)d_cols[1][m][j]*HW2 + hw];
    out[((size_t)(bd*T_DIM + m))*HW2 + hw] = acc;
}

// ============ Pass A: fused resample + W-axis forward (128 real -> 256-pt, keep 129) ============
__global__ __launch_bounds__(256) void k_fft_w_fwd(const float* __restrict__ feature)
{
    __shared__ float2 Xs[16][16][17];   // [line][k2][n1 + pad]
    __shared__ float2 Wtw[256];
    int tid = threadIdx.x;
    Wtw[tid] = d_W256[tid];
    int n1 = tid & 15, ln = tid >> 4;
    int G  = blockIdx.x*16 + ln;        // (bd*256 + m)*128 + h
    int h  = G & 127;
    int m  = (G >> 7) & 255;
    int bd = G >> 15;
    int nnz = d_cnt[0][m];
    float acc[8];
    #pragma unroll
    for (int i = 0; i < 8; i++) acc[i] = 0.f;
    for (int j = 0; j < nnz; j++) {
        float v = d_vals[0][m][j];
        const float* fp = feature + (((size_t)(bd*T_DIM + d_cols[0][m][j]))*HW + h)*HW;
        #pragma unroll
        for (int n2 = 0; n2 < 8; n2++) acc[n2] += v * fp[n1 + 16*n2];
    }
    float2 r[16];
    #pragma unroll
    for (int n2 = 0; n2 < 8; n2++)  r[n2] = make_float2(acc[n2], 0.f);
    #pragma unroll
    for (int n2 = 8; n2 < 16; n2++) r[n2] = make_float2(0.f, 0.f);
    __syncthreads();
    dft16<1>(r);
    #pragma unroll
    for (int s = 0; s < 16; s++) {
        const int k2 = br4(s);
        Xs[ln][k2][n1] = cmul(r[s], Wtw[n1*k2]);
    }
    __syncthreads();
    int k2p = n1;
    #pragma unroll
    for (int j = 0; j < 16; j++) r[j] = Xs[ln][k2p][j];
    dft16<1>(r);
    float2* out = d_bufA + (size_t)G*KWS;
    #pragma unroll
    for (int s = 0; s < 16; s++) {
        const int k1 = br4(s);
        int k = k2p + 16*k1;
        if (k <= 128) out[k] = r[s];
    }
}

// ============ Pass B: H-axis forward (128 -> 256, four-step 16x16 register FFT) ============
__global__ __launch_bounds__(256) void k_fft_h_fwd()
{
    __shared__ float2 Xs[16][17][17];   // [k2][n1][kwl]
    __shared__ float2 Wtw[256];
    int tid = threadIdx.x;
    Wtw[tid] = d_W256[tid];
    int kwl = tid & 15, n1 = tid >> 4;
    int kw = blockIdx.x*16 + kwl;
    bool ok = kw < KW;
    const float2* in = d_bufA + ((size_t)(blockIdx.z*T_DIM + blockIdx.y))*HW*KWS;
    float2 r[16];
    #pragma unroll
    for (int n2 = 0; n2 < 8; n2++)
        r[n2] = ok ? in[(n1 + 16*n2)*KWS + kw] : make_float2(0.f,0.f);
    #pragma unroll
    for (int n2 = 8; n2 < 16; n2++) r[n2] = make_float2(0.f,0.f);
    __syncthreads();
    dft16<1>(r);
    #pragma unroll
    for (int s = 0; s < 16; s++) {
        const int k2 = br4(s);
        Xs[k2][n1][kwl] = cmul(r[s], Wtw[n1*k2]);
    }
    __syncthreads();
    int k2p = n1;
    #pragma unroll
    for (int j = 0; j < 16; j++) r[j] = Xs[k2p][j][kwl];
    dft16<1>(r);
    float2* out = d_bufB + ((size_t)(blockIdx.z*T_DIM + blockIdx.y))*T_DIM*KWS;
    if (ok) {
        #pragma unroll
        for (int s = 0; s < 16; s++) {
            int kh = k2p + 16*br4(s);
            out[kh*KWS + kw] = r[s];
        }
    }
}

// ============ Pass C: T-axis via even/odd split — 4x 256-pt register FFTs ============
// X512[2k] = FFT256(x); X512[2k+1] = FFT256(x*W512^t).
// y[n<256] = IFFT256(Ye')[n] + W512^{-n} * IFFT256(Yo')[n]  (norm folded into psf).
// Block: 256 thr = 16 cols (2 bd x 8 kw) x 16. Grid: (17 kw-tiles, 256 kh).
__global__ __launch_bounds__(256, 2) void k_fft_t(const float* __restrict__ pr, const float* __restrict__ pi)
{
    __shared__ float2 Xs[16][16][17];   // [a][b][col]
    __shared__ float2 Wtw[256];         // W256
    __shared__ float2 W5[256];          // W512^t
    int tid = threadIdx.x;
    Wtw[tid] = d_W256[tid];
    W5[tid]  = d_W512[tid];
    int col = tid & 15, tt = tid >> 4;  // tt = n1 / k2p / n1p (same lane idx across steps)
    int bd = col >> 3, kwl = col & 7;
    int kw = blockIdx.x*8 + kwl;
    int kh = blockIdx.y;
    bool ok = kw < KW;
    const int TSTR = T_DIM*KWS;
    const size_t BDSTR = (size_t)T_DIM*T_DIM*KWS;
    float2* base = d_bufB + (size_t)bd*BDSTR + (size_t)kh*KWS;
    const float NORM = 1.0f / 33554432.0f;   // 1/(512*256*256)
    __syncthreads();                    // twiddle tables ready

    float2 r[16], rin[16], Se[16];

    // ================= EVEN chain: S_e = IFFT256( FFT256(x) * psf[2k] ) =================
    #pragma unroll
    for (int n2 = 0; n2 < 16; n2++)
        r[n2] = ok ? base[(size_t)(tt + 16*n2)*TSTR + kw] : make_float2(0.f,0.f);
    dft16<1>(r);                        // over n2 -> k2 in bitrev slots
    #pragma unroll
    for (int s = 0; s < 16; s++) { const int k2 = br4(s); Xs[k2][tt][col] = cmul(r[s], Wtw[tt*k2]); }
    __syncthreads();
    #pragma unroll
    for (int j = 0; j < 16; j++) r[j] = Xs[tt][j][col];    // thread now owns k2p = tt
    dft16<1>(r);                        // slot s: X256[tt + 16*br4(s)]
    #pragma unroll
    for (int s = 0; s < 16; s++) {      // psf multiply + reg permute into inverse input order
        const int k1 = br4(s);
        int k = tt + 16*k1;
        float2 p = make_float2(0.f,0.f);
        if (ok) { size_t o = ((size_t)(2*k)*256 + kh)*256 + kw; p = make_float2(pr[o]*NORM, pi[o]*NORM); }
        rin[k1] = cmul(r[s], p);
    }
    __syncthreads();                    // Xs reads done, safe to overwrite
    dft16<-1>(rin);                     // over k1 -> n1 in bitrev slots
    #pragma unroll
    for (int s = 0; s < 16; s++) { const int n1 = br4(s); Xs[n1][tt][col] = cmulc(rin[s], Wtw[n1*tt]); }
    __syncthreads();
    #pragma unroll
    for (int j = 0; j < 16; j++) Se[j] = Xs[tt][j][col];   // thread owns n1p = tt
    dft16<-1>(Se);                      // slot s: S_e[tt + 16*br4(s)]
    __syncthreads();                    // before odd chain reuses Xs

    // ================= ODD chain: S_o = IFFT256( FFT256(x*W512^t) * psf[2k+1] ) =================
    #pragma unroll
    for (int n2 = 0; n2 < 16; n2++) {
        int t = tt + 16*n2;
        float2 v = ok ? base[(size_t)t*TSTR + kw] : make_float2(0.f,0.f);
        r[n2] = cmul(v, W5[t]);
    }
    dft16<1>(r);
    #pragma unroll
    for (int s = 0; s < 16; s++) { const int k2 = br4(s); Xs[k2][tt][col] = cmul(r[s], Wtw[tt*k2]); }
    __syncthreads();
    #pragma unroll
    for (int j = 0; j < 16; j++) r[j] = Xs[tt][j][col];
    dft16<1>(r);
    #pragma unroll
    for (int s = 0; s < 16; s++) {
        const int k1 = br4(s);
        int k = tt + 16*k1;
        float2 p = make_float2(0.f,0.f);
        if (ok) { size_t o = ((size_t)(2*k+1)*256 + kh)*256 + kw; p = make_float2(pr[o]*NORM, pi[o]*NORM); }
        rin[k1] = cmul(r[s], p);
    }
    __syncthreads();
    dft16<-1>(rin);
    #pragma unroll
    for (int s = 0; s < 16; s++) { const int n1 = br4(s); Xs[n1][tt][col] = cmulc(rin[s], Wtw[n1*tt]); }
    __syncthreads();
    #pragma unroll
    for (int j = 0; j < 16; j++) r[j] = Xs[tt][j][col];
    dft16<-1>(r);                       // slot s: S_o[tt + 16*br4(s)]

    // ================= combine + store (crop t < 256) =================
    if (ok) {
        #pragma unroll
        for (int s = 0; s < 16; s++) {
            int n = tt + 16*br4(s);
            float2 y = cadd(Se[s], cmulc(r[s], W5[n]));   // + conj(W512^n) * S_o
            base[(size_t)n*TSTR + kw] = y;
        }
    }
}

// ============ Pass D: H-axis inverse (256 -> crop 128, four-step) ============
__global__ __launch_bounds__(256) void k_fft_h_inv()
{
    __shared__ float2 Xs[16][17][17];   // [n1][k2][kwl]
    __shared__ float2 Wtw[256];
    int tid = threadIdx.x;
    Wtw[tid] = d_W256[tid];
    int kwl = tid & 15, k2 = tid >> 4;
    int kw = blockIdx.x*16 + kwl;
    bool ok = kw < KW;
    const float2* in = d_bufB + ((size_t)(blockIdx.z*T_DIM + blockIdx.y))*T_DIM*KWS;
    float2 r[16];
    #pragma unroll
    for (int k1 = 0; k1 < 16; k1++)
        r[k1] = ok ? in[(k2 + 16*k1)*KWS + kw] : make_float2(0.f,0.f);
    __syncthreads();
    dft16<-1>(r);
    #pragma unroll
    for (int s = 0; s < 16; s++) {
        const int n1 = br4(s);
        Xs[n1][k2][kwl] = cmulc(r[s], Wtw[n1*k2]);
    }
    __syncthreads();
    int n1p = k2;
    #pragma unroll
    for (int j = 0; j < 16; j++) r[j] = Xs[n1p][j][kwl];
    dft16<-1>(r);
    float2* out = d_bufA + ((size_t)(blockIdx.z*T_DIM + blockIdx.y))*HW*KWS;
    if (ok) {
        #pragma unroll
        for (int s = 0; s < 16; s++) {
            const int n2 = br4(s);
            if (n2 < 8) out[(n1p + 16*n2)*KWS + kw] = r[s];
        }
    }
}

// ============ Pass E: W-axis inverse C2R (Hermitian 129 -> 256 -> real 128, four-step) ============
__global__ __launch_bounds__(256) void k_fft_w_inv()
{
    __shared__ float2 Xs[16][16][17];   // [line][n1][k2 + pad]
    __shared__ float2 Wtw[256];
    int tid = threadIdx.x;
    Wtw[tid] = d_W256[tid];
    int tt = tid & 15, ln = tid >> 4;
    size_t G = (size_t)blockIdx.x*16 + ln;   // (bd*256 + t)*128 + h
    const float2* in = d_bufA + G*KWS;
    float2 r[16];
    #pragma unroll
    for (int k1 = 0; k1 < 16; k1++) {
        int k = tt + 16*k1;
        float2 v;
        if (k <= 128) v = in[k];
        else { float2 c = in[256-k]; v = make_float2(c.x, -c.y); }
        r[k1] = v;
    }
    __syncthreads();
    dft16<-1>(r);
    #pragma unroll
    for (int s = 0; s < 16; s++) {
        const int n1 = br4(s);
        Xs[ln][n1][tt] = cmulc(r[s], Wtw[n1*tt]);
    }
    __syncthreads();
    int n1p = tt;
    #pragma unroll
    for (int j = 0; j < 16; j++) r[j] = Xs[ln][n1p][j];
    dft16<-1>(r);
    float* outp = d_tmp + G*HW;
    #pragma unroll
    for (int s = 0; s < 16; s++) {
        const int n2 = br4(s);
        if (n2 < 8) outp[n1p + 16*n2] = r[s].x;
    }
}

// ---------------- launch ----------------
extern "C" void kernel_launch(void* const* d_in, const int* in_sizes, int n_in,
                              void* d_out, int out_size)
{
    (void)in_sizes; (void)n_in; (void)out_size;
    const float* feature = (const float*)d_in[0];
    const float* gridz   = (const float*)d_in[1];
    const float* mtx     = (const float*)d_in[2];
    const float* mtxi    = (const float*)d_in[3];
    const float* pr      = (const float*)d_in[4];
    const float* pi      = (const float*)d_in[5];
    float* out = (float*)d_out;

    k_init<<<1, 512>>>(mtx, mtxi, gridz);

    k_fft_w_fwd<<<(BD*T_DIM*HW)/16, 256>>>(feature);         // fused resample + W FFT

    k_fft_h_fwd<<<dim3((KW + 15)/16, T_DIM, BD), 256>>>();

    k_fft_t<<<dim3((KW + 7)/8, T_DIM), 256>>>(pr, pi);       // even/odd split T pass

    k_fft_h_inv<<<dim3((KW + 15)/16, T_DIM, BD), 256>>>();

    k_fft_w_inv<<<(BD*T_DIM*HW)/16, 256>>>();

    k_resample_inv<<<dim3(HW2/256, 256, BD), 256>>>(out);
}